// round 2
// baseline (speedup 1.0000x reference)
#include <cuda_runtime.h>
#include <cuda_bf16.h>
#include <cstdint>

#define MARGIN 1.0f
#define NBLK  1184          // 148 SMs * 8 blocks
#define NTHR  256

// Per-block partials: 6 quantities, laid out [quantity][block] for coalesced
// reads in the finalize kernel. __device__ global => no allocation.
__device__ float g_part[6 * NBLK];

__device__ __forceinline__ float warp_sum(float v) {
    #pragma unroll
    for (int o = 16; o > 0; o >>= 1) v += __shfl_xor_sync(0xFFFFFFFFu, v, o);
    return v;
}

__global__ __launch_bounds__(NTHR) void sqloss_reduce(
    const float* __restrict__ pred, const int* __restrict__ lab, int n)
{
    const float4* __restrict__ p4 = reinterpret_cast<const float4*>(pred);
    const int4*   __restrict__ l4 = reinterpret_cast<const int4*>(lab);
    const int n4 = n >> 2;

    float a = 0.f, sz = 0.f, sz2 = 0.f, sp = 0.f, sp2 = 0.f, nn = 0.f;

    const int stride = gridDim.x * blockDim.x;
    int i = blockIdx.x * blockDim.x + threadIdx.x;

    for (; i < n4; i += stride) {
        float4 pv = p4[i];
        int4   lv = l4[i];

        // branchless per-lane-of-vector processing
        {
            float m = (lv.x == 1) ? 1.f : 0.f;  // positive mask
            float z = m * (MARGIN - pv.x);
            a  += m;  sz += z;  sz2 = fmaf(z, z, sz2);
            float w  = 1.f - m;                  // negative mask
            float pw = w * pv.x;
            nn += w;  sp += pw; sp2 = fmaf(pw, pv.x, sp2);
        }
        {
            float m = (lv.y == 1) ? 1.f : 0.f;
            float z = m * (MARGIN - pv.y);
            a  += m;  sz += z;  sz2 = fmaf(z, z, sz2);
            float w  = 1.f - m;
            float pw = w * pv.y;
            nn += w;  sp += pw; sp2 = fmaf(pw, pv.y, sp2);
        }
        {
            float m = (lv.z == 1) ? 1.f : 0.f;
            float z = m * (MARGIN - pv.z);
            a  += m;  sz += z;  sz2 = fmaf(z, z, sz2);
            float w  = 1.f - m;
            float pw = w * pv.z;
            nn += w;  sp += pw; sp2 = fmaf(pw, pv.z, sp2);
        }
        {
            float m = (lv.w == 1) ? 1.f : 0.f;
            float z = m * (MARGIN - pv.w);
            a  += m;  sz += z;  sz2 = fmaf(z, z, sz2);
            float w  = 1.f - m;
            float pw = w * pv.w;
            nn += w;  sp += pw; sp2 = fmaf(pw, pv.w, sp2);
        }
    }

    // scalar tail (n not multiple of 4) — handled by global thread 0 only
    if (blockIdx.x == 0 && threadIdx.x == 0) {
        for (int j = n4 << 2; j < n; j++) {
            float pv = pred[j];
            float m = (lab[j] == 1) ? 1.f : 0.f;
            float z = m * (MARGIN - pv);
            a  += m;  sz += z;  sz2 = fmaf(z, z, sz2);
            float w  = 1.f - m;
            float pw = w * pv;
            nn += w;  sp += pw; sp2 = fmaf(pw, pv, sp2);
        }
    }

    // block reduction: warp shuffle then shared memory
    __shared__ float sm[6][NTHR / 32];
    float vals[6] = {a, sz, sz2, sp, sp2, nn};
    const int lane = threadIdx.x & 31;
    const int wid  = threadIdx.x >> 5;

    #pragma unroll
    for (int j = 0; j < 6; j++) {
        float v = warp_sum(vals[j]);
        if (lane == 0) sm[j][wid] = v;
    }
    __syncthreads();

    if (wid == 0) {
        #pragma unroll
        for (int j = 0; j < 6; j++) {
            float v = (lane < NTHR / 32) ? sm[j][lane] : 0.f;
            v = warp_sum(v);
            if (lane == 0) g_part[j * NBLK + blockIdx.x] = v;
        }
    }
}

// Finalize: one block of 1024 threads sums NBLK partials per quantity
// (in double) and emits loss = a*sp2 + 2*sz*sp + sz2*nn.
__global__ __launch_bounds__(1024) void sqloss_finalize(float* __restrict__ out)
{
    __shared__ double sm[6][32];
    const int lane = threadIdx.x & 31;
    const int wid  = threadIdx.x >> 5;

    double acc[6];
    #pragma unroll
    for (int j = 0; j < 6; j++) {
        double v = 0.0;
        for (int b = threadIdx.x; b < NBLK; b += 1024)
            v += (double)g_part[j * NBLK + b];
        // warp reduce in double
        #pragma unroll
        for (int o = 16; o > 0; o >>= 1)
            v += __shfl_xor_sync(0xFFFFFFFFu, v, o);
        if (lane == 0) sm[j][wid] = v;
        acc[j] = v;
    }
    __syncthreads();

    if (wid == 0) {
        #pragma unroll
        for (int j = 0; j < 6; j++) {
            double v = (lane < 32) ? sm[j][lane] : 0.0;
            #pragma unroll
            for (int o = 16; o > 0; o >>= 1)
                v += __shfl_xor_sync(0xFFFFFFFFu, v, o);
            acc[j] = v;
        }
        if (lane == 0) {
            double a   = acc[0];
            double sz  = acc[1];
            double sz2 = acc[2];
            double sp  = acc[3];
            double sp2 = acc[4];
            double nn  = acc[5];
            double loss = a * sp2 + 2.0 * sz * sp + sz2 * nn;
            out[0] = (float)loss;
        }
    }
}

extern "C" void kernel_launch(void* const* d_in, const int* in_sizes, int n_in,
                              void* d_out, int out_size)
{
    const float* pred = (const float*)d_in[0];
    const int*   lab  = (const int*)d_in[1];
    float*       out  = (float*)d_out;
    const int n = in_sizes[0];

    sqloss_reduce<<<NBLK, NTHR>>>(pred, lab, n);
    sqloss_finalize<<<1, 1024>>>(out);
}

// round 5
// speedup vs baseline: 1.0358x; 1.0358x over previous
#include <cuda_runtime.h>
#include <cuda_bf16.h>
#include <cstdint>

#define MARGIN 1.0f
#define NBLK  1184          // 148 SMs * 8 blocks
#define NTHR  256

// Per-block partials: 6 quantities, laid out [quantity][block].
// __device__ globals => no allocation (guard-safe).
__device__ float        g_part[6 * NBLK];
__device__ unsigned int g_count = 0;

__device__ __forceinline__ float warp_sum(float v) {
    #pragma unroll
    for (int o = 16; o > 0; o >>= 1) v += __shfl_xor_sync(0xFFFFFFFFu, v, o);
    return v;
}

__device__ __forceinline__ double warp_sum_d(double v) {
    #pragma unroll
    for (int o = 16; o > 0; o >>= 1) v += __shfl_xor_sync(0xFFFFFFFFu, v, o);
    return v;
}

// Accumulate one (pred, label) pair into the six running sums.
__device__ __forceinline__ void acc1(float pv, int lv,
                                     float& a, float& sz, float& sz2,
                                     float& sp, float& sp2, float& nn)
{
    float m = (lv == 1) ? 1.f : 0.f;     // positive mask
    float z = m * (MARGIN - pv);
    a  += m;  sz += z;  sz2 = fmaf(z, z, sz2);
    float w  = 1.f - m;                  // negative mask
    float pw = w * pv;
    nn += w;  sp += pw; sp2 = fmaf(pw, pv, sp2);
}

__global__ __launch_bounds__(NTHR) void sqloss_fused(
    const float* __restrict__ pred, const int* __restrict__ lab, int n,
    float* __restrict__ out)
{
    const float4* __restrict__ p4 = reinterpret_cast<const float4*>(pred);
    const int4*   __restrict__ l4 = reinterpret_cast<const int4*>(lab);
    const int n4 = n >> 2;

    float a = 0.f, sz = 0.f, sz2 = 0.f, sp = 0.f, sp2 = 0.f, nn = 0.f;

    const int stride = gridDim.x * blockDim.x;
    int i = blockIdx.x * blockDim.x + threadIdx.x;

    // 2x unrolled grid-stride: four independent 128-bit loads in flight.
    for (; i + stride < n4; i += 2 * stride) {
        float4 pa = p4[i];
        int4   la = l4[i];
        float4 pb = p4[i + stride];
        int4   lb = l4[i + stride];

        acc1(pa.x, la.x, a, sz, sz2, sp, sp2, nn);
        acc1(pa.y, la.y, a, sz, sz2, sp, sp2, nn);
        acc1(pa.z, la.z, a, sz, sz2, sp, sp2, nn);
        acc1(pa.w, la.w, a, sz, sz2, sp, sp2, nn);
        acc1(pb.x, lb.x, a, sz, sz2, sp, sp2, nn);
        acc1(pb.y, lb.y, a, sz, sz2, sp, sp2, nn);
        acc1(pb.z, lb.z, a, sz, sz2, sp, sp2, nn);
        acc1(pb.w, lb.w, a, sz, sz2, sp, sp2, nn);
    }
    if (i < n4) {
        float4 pa = p4[i];
        int4   la = l4[i];
        acc1(pa.x, la.x, a, sz, sz2, sp, sp2, nn);
        acc1(pa.y, la.y, a, sz, sz2, sp, sp2, nn);
        acc1(pa.z, la.z, a, sz, sz2, sp, sp2, nn);
        acc1(pa.w, la.w, a, sz, sz2, sp, sp2, nn);
    }

    // scalar tail (n not multiple of 4) — global thread 0 only
    if (blockIdx.x == 0 && threadIdx.x == 0) {
        for (int j = n4 << 2; j < n; j++)
            acc1(pred[j], lab[j], a, sz, sz2, sp, sp2, nn);
    }

    // ── block reduction ──
    __shared__ float sm[6][NTHR / 32];
    float vals[6] = {a, sz, sz2, sp, sp2, nn};
    const int lane = threadIdx.x & 31;
    const int wid  = threadIdx.x >> 5;

    #pragma unroll
    for (int j = 0; j < 6; j++) {
        float v = warp_sum(vals[j]);
        if (lane == 0) sm[j][wid] = v;
    }
    __syncthreads();

    if (wid == 0) {
        #pragma unroll
        for (int j = 0; j < 6; j++) {
            float v = (lane < NTHR / 32) ? sm[j][lane] : 0.f;
            v = warp_sum(v);
            if (lane == 0) g_part[j * NBLK + blockIdx.x] = v;
        }
    }

    // ── last-block-done finalize (threadfence reduction) ──
    __shared__ bool amLast;
    __threadfence();                       // make g_part writes visible
    if (threadIdx.x == 0) {
        unsigned int t = atomicAdd(&g_count, 1u);
        amLast = (t == gridDim.x - 1);
    }
    __syncthreads();

    if (amLast) {
        __shared__ double smd[6][NTHR / 32];
        double acc[6];
        #pragma unroll
        for (int j = 0; j < 6; j++) {
            double v = 0.0;
            for (int b = threadIdx.x; b < NBLK; b += NTHR)
                v += (double)g_part[j * NBLK + b];
            v = warp_sum_d(v);
            if (lane == 0) smd[j][wid] = v;
        }
        __syncthreads();
        if (wid == 0) {
            #pragma unroll
            for (int j = 0; j < 6; j++) {
                double v = (lane < NTHR / 32) ? smd[j][lane] : 0.0;
                acc[j] = warp_sum_d(v);
            }
            if (lane == 0) {
                double A   = acc[0];
                double SZ  = acc[1];
                double SZ2 = acc[2];
                double SP  = acc[3];
                double SP2 = acc[4];
                double NN  = acc[5];
                out[0] = (float)(A * SP2 + 2.0 * SZ * SP + SZ2 * NN);
                g_count = 0;               // reset for next graph replay
            }
        }
    }
}

extern "C" void kernel_launch(void* const* d_in, const int* in_sizes, int n_in,
                              void* d_out, int out_size)
{
    const float* pred = (const float*)d_in[0];
    const int*   lab  = (const int*)d_in[1];
    float*       out  = (float*)d_out;
    const int n = in_sizes[0];

    sqloss_fused<<<NBLK, NTHR>>>(pred, lab, n, out);
}

// round 8
// speedup vs baseline: 1.0731x; 1.0360x over previous
#include <cuda_runtime.h>
#include <cuda_bf16.h>
#include <cstdint>

#define MARGIN 1.0f
#define NBLK  1184          // 148 SMs * 8 blocks
#define NTHR  256
#define NQ    5             // a, sz, sz2, S, S2

// Per-block partials, [quantity][block]. __device__ globals => no allocation.
__device__ float        g_part[NQ * NBLK];
__device__ unsigned int g_count = 0;

__device__ __forceinline__ float warp_sum(float v) {
    #pragma unroll
    for (int o = 16; o > 0; o >>= 1) v += __shfl_xor_sync(0xFFFFFFFFu, v, o);
    return v;
}

__device__ __forceinline__ double warp_sum_d(double v) {
    #pragma unroll
    for (int o = 16; o > 0; o >>= 1) v += __shfl_xor_sync(0xFFFFFFFFu, v, o);
    return v;
}

// Per-element update: unmasked S, S2; masked a, sz, sz2 (positives only).
__device__ __forceinline__ void acc1(float pv, int lv,
                                     float& a, float& sz, float& sz2,
                                     float& S, float& S2)
{
    S  += pv;
    S2  = fmaf(pv, pv, S2);
    float m = (lv == 1) ? 1.f : 0.f;     // positive mask
    float z = m * (MARGIN - pv);
    a  += m;
    sz += z;
    sz2 = fmaf(z, z, sz2);
}

__global__ __launch_bounds__(NTHR) void sqloss_fused(
    const float* __restrict__ pred, const int* __restrict__ lab, int n,
    float* __restrict__ out)
{
    const float4* __restrict__ p4 = reinterpret_cast<const float4*>(pred);
    const int4*   __restrict__ l4 = reinterpret_cast<const int4*>(lab);
    const int n4 = n >> 2;

    float a = 0.f, sz = 0.f, sz2 = 0.f, S = 0.f, S2 = 0.f;

    const int stride = gridDim.x * blockDim.x;

    // Simple grid-stride: one 128-bit pred load + one 128-bit label load per
    // iteration (the R1 structure that hit ~80% of HBM). Streaming hint:
    // data is touched exactly once.
    for (int i = blockIdx.x * blockDim.x + threadIdx.x; i < n4; i += stride) {
        float4 pv = __ldcs(&p4[i]);
        int4   lv = __ldcs(&l4[i]);
        acc1(pv.x, lv.x, a, sz, sz2, S, S2);
        acc1(pv.y, lv.y, a, sz, sz2, S, S2);
        acc1(pv.z, lv.z, a, sz, sz2, S, S2);
        acc1(pv.w, lv.w, a, sz, sz2, S, S2);
    }

    // scalar tail (n not multiple of 4) — global thread 0 only
    if (blockIdx.x == 0 && threadIdx.x == 0) {
        for (int j = n4 << 2; j < n; j++)
            acc1(pred[j], lab[j], a, sz, sz2, S, S2);
    }

    // ── block reduction ──
    __shared__ float sm[NQ][NTHR / 32];
    float vals[NQ] = {a, sz, sz2, S, S2};
    const int lane = threadIdx.x & 31;
    const int wid  = threadIdx.x >> 5;

    #pragma unroll
    for (int j = 0; j < NQ; j++) {
        float v = warp_sum(vals[j]);
        if (lane == 0) sm[j][wid] = v;
    }
    __syncthreads();

    if (wid == 0) {
        #pragma unroll
        for (int j = 0; j < NQ; j++) {
            float v = (lane < NTHR / 32) ? sm[j][lane] : 0.f;
            v = warp_sum(v);
            if (lane == 0) g_part[j * NBLK + blockIdx.x] = v;
        }
    }

    // ── last-block-done finalize ──
    __shared__ bool amLast;
    __threadfence();
    if (threadIdx.x == 0) {
        unsigned int t = atomicAdd(&g_count, 1u);
        amLast = (t == gridDim.x - 1);
    }
    __syncthreads();

    if (amLast) {
        __shared__ double smd[NQ][NTHR / 32];
        double acc[NQ];
        #pragma unroll
        for (int j = 0; j < NQ; j++) {
            double v = 0.0;
            for (int b = threadIdx.x; b < NBLK; b += NTHR)
                v += (double)g_part[j * NBLK + b];
            v = warp_sum_d(v);
            if (lane == 0) smd[j][wid] = v;
        }
        __syncthreads();
        if (wid == 0) {
            #pragma unroll
            for (int j = 0; j < NQ; j++) {
                double v = (lane < NTHR / 32) ? smd[j][lane] : 0.0;
                acc[j] = warp_sum_d(v);
            }
            if (lane == 0) {
                double A   = acc[0];
                double SZ  = acc[1];
                double SZ2 = acc[2];
                double S   = acc[3];
                double S2  = acc[4];
                // Derived masked-negative sums:
                double NN  = (double)n - A;              // n_neg
                double SP  = S  - (A - SZ);              // sum_neg p
                double SP2 = S2 - (A - 2.0 * SZ + SZ2);  // sum_neg p^2
                out[0] = (float)(A * SP2 + 2.0 * SZ * SP + SZ2 * NN);
                g_count = 0;   // reset for next graph replay
            }
        }
    }
}

extern "C" void kernel_launch(void* const* d_in, const int* in_sizes, int n_in,
                              void* d_out, int out_size)
{
    const float* pred = (const float*)d_in[0];
    const int*   lab  = (const int*)d_in[1];
    float*       out  = (float*)d_out;
    const int n = in_sizes[0];

    sqloss_fused<<<NBLK, NTHR>>>(pred, lab, n, out);
}

// round 9
// speedup vs baseline: 1.1583x; 1.0795x over previous
#include <cuda_runtime.h>
#include <cuda_bf16.h>
#include <cstdint>

#define MARGIN 1.0f
#define NBLK  592           // 148 SMs * 4 blocks -> exactly one wave
#define NTHR  256
#define NQ    5             // a, sz, sz2, S, S2

// Per-block partials, [quantity][block]. __device__ globals => no allocation.
__device__ float        g_part[NQ * NBLK];
__device__ unsigned int g_count = 0;

__device__ __forceinline__ float warp_sum(float v) {
    #pragma unroll
    for (int o = 16; o > 0; o >>= 1) v += __shfl_xor_sync(0xFFFFFFFFu, v, o);
    return v;
}

__device__ __forceinline__ double warp_sum_d(double v) {
    #pragma unroll
    for (int o = 16; o > 0; o >>= 1) v += __shfl_xor_sync(0xFFFFFFFFu, v, o);
    return v;
}

// Per-element update: unmasked S, S2; masked a, sz, sz2 (positives only).
__device__ __forceinline__ void acc1(float pv, int lv,
                                     float& a, float& sz, float& sz2,
                                     float& S, float& S2)
{
    S  += pv;
    S2  = fmaf(pv, pv, S2);
    float m = (lv == 1) ? 1.f : 0.f;     // positive mask
    float z = m * (MARGIN - pv);
    a  += m;
    sz += z;
    sz2 = fmaf(z, z, sz2);
}

__device__ __forceinline__ void acc4(const float4& pv, const int4& lv,
                                     float& a, float& sz, float& sz2,
                                     float& S, float& S2)
{
    acc1(pv.x, lv.x, a, sz, sz2, S, S2);
    acc1(pv.y, lv.y, a, sz, sz2, S, S2);
    acc1(pv.z, lv.z, a, sz, sz2, S, S2);
    acc1(pv.w, lv.w, a, sz, sz2, S, S2);
}

// 4 blocks/SM cap -> 64-register budget -> room to front-batch 8 LDG.128.
__global__ __launch_bounds__(NTHR, 4) void sqloss_fused(
    const float* __restrict__ pred, const int* __restrict__ lab, int n,
    float* __restrict__ out)
{
    const float4* __restrict__ p4 = reinterpret_cast<const float4*>(pred);
    const int4*   __restrict__ l4 = reinterpret_cast<const int4*>(lab);
    const int n4 = n >> 2;

    float a = 0.f, sz = 0.f, sz2 = 0.f, S = 0.f, S2 = 0.f;

    const int stride = gridDim.x * blockDim.x;
    int i = blockIdx.x * blockDim.x + threadIdx.x;

    // 4x unrolled grid-stride: eight independent 128-bit streaming loads
    // issued back-to-back (MLP_p1 = 8), then the arithmetic.
    for (; i + 3 * stride < n4; i += 4 * stride) {
        float4 p0 = __ldcs(&p4[i]);
        float4 p1 = __ldcs(&p4[i +     stride]);
        float4 p2 = __ldcs(&p4[i + 2 * stride]);
        float4 p3 = __ldcs(&p4[i + 3 * stride]);
        int4   l0 = __ldcs(&l4[i]);
        int4   l1 = __ldcs(&l4[i +     stride]);
        int4   l2 = __ldcs(&l4[i + 2 * stride]);
        int4   l3 = __ldcs(&l4[i + 3 * stride]);

        acc4(p0, l0, a, sz, sz2, S, S2);
        acc4(p1, l1, a, sz, sz2, S, S2);
        acc4(p2, l2, a, sz, sz2, S, S2);
        acc4(p3, l3, a, sz, sz2, S, S2);
    }
    // vector remainder
    for (; i < n4; i += stride) {
        float4 pv = __ldcs(&p4[i]);
        int4   lv = __ldcs(&l4[i]);
        acc4(pv, lv, a, sz, sz2, S, S2);
    }

    // scalar tail (n not multiple of 4) — global thread 0 only
    if (blockIdx.x == 0 && threadIdx.x == 0) {
        for (int j = n4 << 2; j < n; j++)
            acc1(pred[j], lab[j], a, sz, sz2, S, S2);
    }

    // ── block reduction ──
    __shared__ float sm[NQ][NTHR / 32];
    float vals[NQ] = {a, sz, sz2, S, S2};
    const int lane = threadIdx.x & 31;
    const int wid  = threadIdx.x >> 5;

    #pragma unroll
    for (int j = 0; j < NQ; j++) {
        float v = warp_sum(vals[j]);
        if (lane == 0) sm[j][wid] = v;
    }
    __syncthreads();

    if (wid == 0) {
        #pragma unroll
        for (int j = 0; j < NQ; j++) {
            float v = (lane < NTHR / 32) ? sm[j][lane] : 0.f;
            v = warp_sum(v);
            if (lane == 0) g_part[j * NBLK + blockIdx.x] = v;
        }
    }

    // ── last-block-done finalize ──
    __shared__ bool amLast;
    __threadfence();
    if (threadIdx.x == 0) {
        unsigned int t = atomicAdd(&g_count, 1u);
        amLast = (t == gridDim.x - 1);
    }
    __syncthreads();

    if (amLast) {
        __shared__ double smd[NQ][NTHR / 32];
        double acc[NQ];
        #pragma unroll
        for (int j = 0; j < NQ; j++) {
            double v = 0.0;
            for (int b = threadIdx.x; b < NBLK; b += NTHR)
                v += (double)g_part[j * NBLK + b];
            v = warp_sum_d(v);
            if (lane == 0) smd[j][wid] = v;
        }
        __syncthreads();
        if (wid == 0) {
            #pragma unroll
            for (int j = 0; j < NQ; j++) {
                double v = (lane < NTHR / 32) ? smd[j][lane] : 0.0;
                acc[j] = warp_sum_d(v);
            }
            if (lane == 0) {
                double A   = acc[0];
                double SZ  = acc[1];
                double SZ2 = acc[2];
                double Sd  = acc[3];
                double S2d = acc[4];
                // Derived masked-negative sums:
                double NN  = (double)n - A;                // n_neg
                double SP  = Sd  - (A - SZ);               // sum_neg p
                double SP2 = S2d - (A - 2.0 * SZ + SZ2);   // sum_neg p^2
                out[0] = (float)(A * SP2 + 2.0 * SZ * SP + SZ2 * NN);
                g_count = 0;   // reset for next graph replay
            }
        }
    }
}

extern "C" void kernel_launch(void* const* d_in, const int* in_sizes, int n_in,
                              void* d_out, int out_size)
{
    const float* pred = (const float*)d_in[0];
    const int*   lab  = (const int*)d_in[1];
    float*       out  = (float*)d_out;
    const int n = in_sizes[0];

    sqloss_fused<<<NBLK, NTHR>>>(pred, lab, n, out);
}

// round 12
// speedup vs baseline: 1.1634x; 1.0043x over previous
#include <cuda_runtime.h>
#include <cuda_bf16.h>
#include <cstdint>

#define MARGIN 1.0f
#define NBLK  592           // 148 SMs * 4 blocks -> exactly one wave
#define NTHR  256
#define NQ    5             // a, sz, sz2, S, S2

// Per-block partials, [quantity][block]. __device__ globals => no allocation.
__device__ float        g_part[NQ * NBLK];
__device__ unsigned int g_count = 0;

__device__ __forceinline__ float warp_sum(float v) {
    #pragma unroll
    for (int o = 16; o > 0; o >>= 1) v += __shfl_xor_sync(0xFFFFFFFFu, v, o);
    return v;
}

__device__ __forceinline__ double warp_sum_d(double v) {
    #pragma unroll
    for (int o = 16; o > 0; o >>= 1) v += __shfl_xor_sync(0xFFFFFFFFu, v, o);
    return v;
}

// Per-element update: unmasked S, S2; masked a, sz, sz2 (positives only).
__device__ __forceinline__ void acc1(float pv, int lv,
                                     float& a, float& sz, float& sz2,
                                     float& S, float& S2)
{
    S  += pv;
    S2  = fmaf(pv, pv, S2);
    float m = (lv == 1) ? 1.f : 0.f;     // positive mask
    float z = m * (MARGIN - pv);
    a  += m;
    sz += z;
    sz2 = fmaf(z, z, sz2);
}

__device__ __forceinline__ void acc4(const float4& pv, const int4& lv,
                                     float& a, float& sz, float& sz2,
                                     float& S, float& S2)
{
    acc1(pv.x, lv.x, a, sz, sz2, S, S2);
    acc1(pv.y, lv.y, a, sz, sz2, S, S2);
    acc1(pv.z, lv.z, a, sz, sz2, S, S2);
    acc1(pv.w, lv.w, a, sz, sz2, S, S2);
}

// 4 blocks/SM cap -> 64-register budget -> 8 front-batched LDG.128 fit.
__global__ __launch_bounds__(NTHR, 4) void sqloss_fused(
    const float* __restrict__ pred, const int* __restrict__ lab, int n,
    float* __restrict__ out)
{
    const float4* __restrict__ p4 = reinterpret_cast<const float4*>(pred);
    const int4*   __restrict__ l4 = reinterpret_cast<const int4*>(lab);
    const int n4 = n >> 2;

    float a = 0.f, sz = 0.f, sz2 = 0.f, S = 0.f, S2 = 0.f;

    const int lane = threadIdx.x & 31;
    const int wid  = threadIdx.x >> 5;

    // ── warp-contiguous segment loop ──
    // Each warp-iteration covers 128 consecutive float4 (2KB pred + 2KB lab,
    // contiguous): lanes at base+0/32/64/96. Perfect per-instruction
    // coalescing AND per-warp DRAM row locality; 8 loads in flight.
    const int warpsTotal = gridDim.x * (NTHR >> 5);
    const int nSeg = n4 >> 7;            // segments of 128 float4
    for (int s = blockIdx.x * (NTHR >> 5) + wid; s < nSeg; s += warpsTotal) {
        const int base = (s << 7) + lane;
        float4 p0 = __ldcs(&p4[base]);
        float4 p1 = __ldcs(&p4[base + 32]);
        float4 p2 = __ldcs(&p4[base + 64]);
        float4 p3 = __ldcs(&p4[base + 96]);
        int4   l0 = __ldcs(&l4[base]);
        int4   l1 = __ldcs(&l4[base + 32]);
        int4   l2 = __ldcs(&l4[base + 64]);
        int4   l3 = __ldcs(&l4[base + 96]);

        acc4(p0, l0, a, sz, sz2, S, S2);
        acc4(p1, l1, a, sz, sz2, S, S2);
        acc4(p2, l2, a, sz, sz2, S, S2);
        acc4(p3, l3, a, sz, sz2, S, S2);
    }

    // vector remainder (n4 not multiple of 128) — grid-linear
    {
        const int gtid = blockIdx.x * NTHR + threadIdx.x;
        for (int i = (nSeg << 7) + gtid; i < n4; i += gridDim.x * NTHR) {
            float4 pv = __ldcs(&p4[i]);
            int4   lv = __ldcs(&l4[i]);
            acc4(pv, lv, a, sz, sz2, S, S2);
        }
    }

    // scalar tail (n not multiple of 4) — global thread 0 only
    if (blockIdx.x == 0 && threadIdx.x == 0) {
        for (int j = n4 << 2; j < n; j++)
            acc1(pred[j], lab[j], a, sz, sz2, S, S2);
    }

    // ── block reduction ──
    __shared__ float sm[NQ][NTHR / 32];
    float vals[NQ] = {a, sz, sz2, S, S2};

    #pragma unroll
    for (int j = 0; j < NQ; j++) {
        float v = warp_sum(vals[j]);
        if (lane == 0) sm[j][wid] = v;
    }
    __syncthreads();

    if (wid == 0) {
        #pragma unroll
        for (int j = 0; j < NQ; j++) {
            float v = (lane < NTHR / 32) ? sm[j][lane] : 0.f;
            v = warp_sum(v);
            if (lane == 0) g_part[j * NBLK + blockIdx.x] = v;
        }
    }

    // ── last-block-done finalize ──
    __shared__ bool amLast;
    __threadfence();
    if (threadIdx.x == 0) {
        unsigned int t = atomicAdd(&g_count, 1u);
        amLast = (t == gridDim.x - 1);
    }
    __syncthreads();

    if (amLast) {
        __shared__ double smd[NQ][NTHR / 32];
        double acc[NQ];
        #pragma unroll
        for (int j = 0; j < NQ; j++) {
            double v = 0.0;
            for (int b = threadIdx.x; b < NBLK; b += NTHR)
                v += (double)g_part[j * NBLK + b];
            v = warp_sum_d(v);
            if (lane == 0) smd[j][wid] = v;
        }
        __syncthreads();
        if (wid == 0) {
            #pragma unroll
            for (int j = 0; j < NQ; j++) {
                double v = (lane < NTHR / 32) ? smd[j][lane] : 0.0;
                acc[j] = warp_sum_d(v);
            }
            if (lane == 0) {
                double A   = acc[0];
                double SZ  = acc[1];
                double SZ2 = acc[2];
                double Sd  = acc[3];
                double S2d = acc[4];
                // Derived masked-negative sums:
                double NN  = (double)n - A;                // n_neg
                double SP  = Sd  - (A - SZ);               // sum_neg p
                double SP2 = S2d - (A - 2.0 * SZ + SZ2);   // sum_neg p^2
                out[0] = (float)(A * SP2 + 2.0 * SZ * SP + SZ2 * NN);
                g_count = 0;   // reset for next graph replay
            }
        }
    }
}

extern "C" void kernel_launch(void* const* d_in, const int* in_sizes, int n_in,
                              void* d_out, int out_size)
{
    const float* pred = (const float*)d_in[0];
    const int*   lab  = (const int*)d_in[1];
    float*       out  = (float*)d_out;
    const int n = in_sizes[0];

    sqloss_fused<<<NBLK, NTHR>>>(pred, lab, n, out);
}